// round 15
// baseline (speedup 1.0000x reference)
#include <cuda_runtime.h>
#include <math.h>

#define N_ANCH 21840
#define NCTILE 683            // max compacted tiles = ceil(21840/32)
#define NSTATE 683            // ceil(21840/32), 2 bits per rank
#define NBLK   86             // ceil(21840/256)
#define NDIG   2048           // 11-bit digit space (valid keys only reach 0x7FF)
#define NCHUNK 8              // candidate-tile chunks (mod-8 strided)
#define SEGCAP 192            // per-(rank,chunk) list capacity (>= old total cap)
#define NRB    64             // resolve blocks
#define NRW    (NRB * 8)      // resolve warps
#define NMS_THF 0.3f
#define FIN_THF 0.5f
#define FULLM 0xFFFFFFFFu

// ---- static device scratch (zero at module load; g_hist/g_state re-zeroed per replay) ----
__device__ float4 g_box[N_ANCH];        // x1,y1,x2,y2 (by original index)
__device__ float g_sc[N_ANCH];
__device__ unsigned g_key[N_ANCH];
__device__ int g_bcnt[NBLK], g_boff[NBLK];
__device__ int g_hist[NDIG];            // re-zeroed by k_resolve each replay
__device__ int g_base[NDIG], g_cursor[NDIG];
__device__ unsigned g_bin[N_ANCH];      // (low12 << 15) | cpos
__device__ float4 g_cbox[N_ANCH];       // compacted valid boxes (index order)
__device__ float2 g_cra[N_ANCH];        // cpos -> (area, rank-as-int-bits)
__device__ unsigned short g_cidx[N_ANCH];  // cpos -> original index
__device__ unsigned short g_ridx[N_ANCH];  // rank -> original index
__device__ int g_kcnt;
__device__ float4 g_tbb[NCTILE];        // compacted tile bbox
__device__ float2 g_tar[NCTILE];        // compacted tile area min/max
__device__ unsigned short g_nbr[(size_t)N_ANCH * NCHUNK * SEGCAP];  // segmented, by rank
__device__ unsigned char g_ncnt8[N_ANCH * NCHUNK];                   // per-segment counts
__device__ unsigned long long g_state[NSTATE];           // 2 bits/rank (resolved, kept)

struct InPtrs { const float* cls[6]; const float* reg[6]; };

// exact area formula shared by all phases (bit-identical everywhere)
__device__ __forceinline__ float box_area(float x1, float y1, float x2, float y2) {
    return __fmul_rn(__fadd_rn(__fsub_rn(x2, x1), 1.0f),
                     __fadd_rn(__fsub_rn(y2, y1), 1.0f));
}

// ---------------- K1: decode (bit-exact) + key + hist + block valid count ----------------
__global__ void k_decode(InPtrs in, float* __restrict__ out) {
    __shared__ int bc;
    int t = threadIdx.x;
    int i = blockIdx.x * 256 + t;
    int lane = t & 31;
    bool on = i < N_ANCH;
    if (t == 0) bc = 0;
    __syncthreads();

    bool valid = false;
    if (on) {
        const int offs[7]   = {0, 16384, 20480, 21504, 21760, 21824, 21840};
        const int maps[6]   = {128, 64, 32, 16, 8, 4};
        const float strd[6] = {4.f, 8.f, 16.f, 32.f, 64.f, 128.f};
        int sc = 0;
        #pragma unroll
        for (int k = 0; k < 5; k++) if (i >= offs[k + 1]) sc = k + 1;
        int local = i - offs[sc];
        int W = maps[sc];
        int y = local / W, x = local - y * W;
        int HW = W * W;
        const float* cls = in.cls[sc];
        const float* reg = in.reg[sc];

        float c0 = cls[local], c1 = cls[HW + local];
        float m  = fmaxf(c0, c1);
        float e0 = expf(__fsub_rn(c0, m));
        float e1 = expf(__fsub_rn(c1, m));
        float prob = __fdiv_rn(e1, __fadd_rn(e0, e1));

        float s   = strd[sc];
        float pwh = s * 4.0f;
        float pcx = __fadd_rn(0.5f * s, __fmul_rn((float)x, s));
        float pcy = __fadd_rn(0.5f * s, __fmul_rn((float)y, s));
        float l0 = reg[local], l1 = reg[HW + local];
        float l2 = reg[2 * HW + local], l3 = reg[3 * HW + local];
        float cx = __fadd_rn(pcx, __fmul_rn(__fmul_rn(l0, 0.1f), pwh));
        float cy = __fadd_rn(pcy, __fmul_rn(__fmul_rn(l1, 0.1f), pwh));
        float w  = __fmul_rn(pwh, expf(__fmul_rn(l2, 0.2f)));
        float h  = __fmul_rn(pwh, expf(__fmul_rn(l3, 0.2f)));
        float x1 = __fsub_rn(cx, __fmul_rn(w, 0.5f));
        float y1 = __fsub_rn(cy, __fmul_rn(h, 0.5f));
        float x2 = __fadd_rn(x1, w);
        float y2 = __fadd_rn(y1, h);

        g_box[i] = make_float4(x1, y1, x2, y2);
        g_sc[i] = prob;

        unsigned u   = __float_as_uint(prob);
        unsigned k24 = (~(u | 0x80000000u)) - 0x407FFFFFu;
        valid = prob > FIN_THF;
        g_key[i] = valid ? k24 : 0xFFFFFFFFu;
        if (valid) {
            atomicAdd(&g_hist[k24 >> 12], 1);
        } else {
            out[i * 5 + 0] = 0.f; out[i * 5 + 1] = 0.f; out[i * 5 + 2] = 0.f;
            out[i * 5 + 3] = 0.f; out[i * 5 + 4] = 0.f;
        }
    }
    unsigned bal = __ballot_sync(FULLM, valid);
    if (lane == 0) atomicAdd(&bc, __popc(bal));
    __syncthreads();
    if (t == 0) g_bcnt[blockIdx.x] = bc;
}

// ---------------- K2: exclusive scans (2048 digits + 86 block counts) ----------------
__global__ void __launch_bounds__(1024) k_scan() {
    __shared__ int wsum[32];
    int t = threadIdx.x, lane = t & 31, wid = t >> 5;

    if (wid == 1) {
        int v0 = (lane < NBLK) ? g_bcnt[lane] : 0;
        int v1 = (lane + 32 < NBLK) ? g_bcnt[lane + 32] : 0;
        int v2 = (lane + 64 < NBLK) ? g_bcnt[lane + 64] : 0;
        int s0 = v0, s1 = v1, s2 = v2;
        #pragma unroll
        for (int k = 1; k < 32; k <<= 1) {
            int a = __shfl_up_sync(FULLM, s0, k); if (lane >= k) s0 += a;
            int b = __shfl_up_sync(FULLM, s1, k); if (lane >= k) s1 += b;
            int c = __shfl_up_sync(FULLM, s2, k); if (lane >= k) s2 += c;
        }
        int t0 = __shfl_sync(FULLM, s0, 31);
        int t1 = __shfl_sync(FULLM, s1, 31);
        if (lane < NBLK) g_boff[lane] = s0 - v0;
        if (lane + 32 < NBLK) g_boff[lane + 32] = t0 + s1 - v1;
        if (lane + 64 < NBLK) g_boff[lane + 64] = t0 + t1 + s2 - v2;
    }

    int a0 = g_hist[2 * t], a1 = g_hist[2 * t + 1];
    int s = a0 + a1;
    int x = s;
    #pragma unroll
    for (int k = 1; k < 32; k <<= 1) { int y = __shfl_up_sync(FULLM, x, k); if (lane >= k) x += y; }
    if (lane == 31) wsum[wid] = x;
    __syncthreads();
    if (wid == 0) {
        int wv = wsum[lane];
        #pragma unroll
        for (int k = 1; k < 32; k <<= 1) { int y = __shfl_up_sync(FULLM, wv, k); if (lane >= k) wv += y; }
        wsum[lane] = wv;
    }
    __syncthreads();
    int base = x - s + ((wid > 0) ? wsum[wid - 1] : 0);
    g_base[2 * t] = base;          g_cursor[2 * t] = base;
    g_base[2 * t + 1] = base + a0; g_cursor[2 * t + 1] = base + a0;
    if (t == 1023) g_kcnt = base + s;   // total valid
}

// ---------------- K3: bin scatter + ordered compaction (+ state zero) ----------------
__global__ void k_scatter() {
    __shared__ int wscan[8];
    if (blockIdx.x == 0) {
        for (int w = threadIdx.x; w < NSTATE; w += 256) g_state[w] = 0ull;
    }
    int t = threadIdx.x, lane = t & 31, wid = t >> 5;
    int i = blockIdx.x * 256 + t;
    bool on = i < N_ANCH;
    unsigned k = on ? g_key[i] : 0xFFFFFFFFu;
    bool valid = (k != 0xFFFFFFFFu);

    unsigned bal = __ballot_sync(FULLM, valid);
    if (lane == 0) wscan[wid] = __popc(bal);
    __syncthreads();
    if (t == 0) {
        int run = 0;
        #pragma unroll
        for (int w = 0; w < 8; w++) { int c = wscan[w]; wscan[w] = run; run += c; }
    }
    __syncthreads();

    if (valid) {
        int cpos = g_boff[blockIdx.x] + wscan[wid] + __popc(bal & ((1u << lane) - 1));
        float4 b = g_box[i];
        g_cbox[cpos] = b;
        g_cra[cpos] = make_float2(box_area(b.x, b.y, b.z, b.w), 0.f);  // rank patched by binsort
        g_cidx[cpos] = (unsigned short)i;
        int d = k >> 12;
        int pos = atomicAdd(&g_cursor[d], 1);
        g_bin[pos] = ((k & 0xFFFu) << 15) | (unsigned)cpos;   // cpos monotone in idx -> stable ties
    }
}

// ---------------- K4: in-bin ranking (warp per bin) + compacted tile bboxes ----------------
__global__ void k_binsort() {
    int wid = threadIdx.x >> 5, lane = threadIdx.x & 31;
    int gw = blockIdx.x * 8 + wid;
    int* rankslot = (int*)g_cra;   // rank lives in .y of float2
    if (gw < NDIG) {
        int d = gw;
        int base = g_base[d];
        int n = g_cursor[d] - base;
        if (n == 0) return;
        if (n <= 32) {
            unsigned rec = (lane < n) ? g_bin[base + lane] : 0xFFFFFFFFu;
            int r = 0;
            for (int k = 0; k < n; k++) {
                unsigned other = __shfl_sync(FULLM, rec, k);
                r += (other < rec) ? 1 : 0;
            }
            if (lane < n) {
                int cpos = rec & 0x7FFFu;
                int rank = base + r;
                rankslot[2 * cpos + 1] = rank;
                g_ridx[rank] = g_cidx[cpos];
            }
        } else {
            for (int e = lane; e < n; e += 32) {
                unsigned rec = g_bin[base + e];
                int r = 0;
                for (int k = 0; k < n; k++) r += (g_bin[base + k] < rec) ? 1 : 0;
                int cpos = rec & 0x7FFFu;
                int rank = base + r;
                rankslot[2 * cpos + 1] = rank;
                g_ridx[rank] = g_cidx[cpos];
            }
        }
    } else {
        int tile = gw - NDIG;
        if (tile >= NCTILE) return;
        int kcnt = g_kcnt;
        int kk = tile * 32 + lane;
        bool on = kk < kcnt;
        float x1 = 0.f, y1 = 0.f, x2 = 0.f, y2 = 0.f, area = 0.f;
        if (on) {
            float4 b = g_cbox[kk];
            x1 = b.x; y1 = b.y; x2 = b.z; y2 = b.w;
            area = box_area(x1, y1, x2, y2);
        }
        float r0 = on ? x1 :  1e30f;
        float r1 = on ? y1 :  1e30f;
        float r2 = on ? x2 : -1e30f;
        float r3 = on ? y2 : -1e30f;
        float r4 = on ? area :  1e30f;
        float r5 = on ? area : -1e30f;
        #pragma unroll
        for (int s = 16; s > 0; s >>= 1) {
            r0 = fminf(r0, __shfl_xor_sync(FULLM, r0, s));
            r1 = fminf(r1, __shfl_xor_sync(FULLM, r1, s));
            r2 = fmaxf(r2, __shfl_xor_sync(FULLM, r2, s));
            r3 = fmaxf(r3, __shfl_xor_sync(FULLM, r3, s));
            r4 = fminf(r4, __shfl_xor_sync(FULLM, r4, s));
            r5 = fmaxf(r5, __shfl_xor_sync(FULLM, r5, s));
        }
        if (lane == 0) {
            g_tbb[tile] = make_float4(r0, r1, r2, r3);
            g_tar[tile] = make_float2(r4, r5);
        }
    }
}

// ---------------- K5: blocked all-pairs suppressor lists ----------------
// warp = (query-tile qt, chunk). 32 queries in lanes; candidates of elected
// tiles loaded once (coalesced) and broadcast via shfl. Chunks take candidate
// tiles ct ≡ chunk (mod 8), so adjacent tiles land in different chunks.
__global__ void k_nbr() {
    int gw = (blockIdx.x * blockDim.x + threadIdx.x) >> 5;
    int lane = threadIdx.x & 31;
    int kcnt = g_kcnt;
    int ntile = (kcnt + 31) >> 5;
    int qt = gw >> 3, chunk = gw & 7;
    if (qt >= ntile) return;

    int q = qt * 32 + lane;
    bool qon = q < kcnt;
    float2 me = qon ? g_cra[q] : make_float2(0.f, 0.f);
    float ai = me.x;
    int ri = qon ? __float_as_int(me.y) : -1;   // -1: rj < ri never true
    float4 bq = qon ? g_cbox[q] : make_float4(0.f, 0.f, 0.f, 0.f);
    float x1 = bq.x, y1 = bq.y, x2 = bq.z, y2 = bq.w;

    // warp-max rank for candidate prefilter
    int rimax = ri;
    #pragma unroll
    for (int s = 16; s > 0; s >>= 1)
        rimax = max(rimax, __shfl_xor_sync(FULLM, rimax, s));

    float4 qb = g_tbb[qt];   // uniform
    float2 qa = g_tar[qt];

    int cnt = 0;
    int nct = (ntile - chunk + NCHUNK - 1) >> 3;   // tiles in this chunk
    for (int tb = 0; tb < nct; tb += 32) {
        int ti = tb + lane;
        bool act = false;
        if (ti < nct) {
            int ct = chunk + ti * NCHUNK;
            float4 cb = g_tbb[ct];
            float2 ca = g_tar[ct];
            float bw = __fadd_rn(__fsub_rn(fminf(qb.z, cb.z), fmaxf(qb.x, cb.x)), 1.0f);
            float bh = __fadd_rn(__fsub_rn(fminf(qb.w, cb.w), fmaxf(qb.y, cb.y)), 1.0f);
            float lo = fminf(qa.y, ca.y);
            float hi = fmaxf(qa.x, ca.x);
            act = (bw > 0.f) && (bh > 0.f) && (lo > 0.299f * hi);
        }
        unsigned bal = __ballot_sync(FULLM, act);
        while (bal) {
            int tt = __ffs(bal) - 1;
            bal &= bal - 1;
            int ct = chunk + (tb + tt) * NCHUNK;
            float4 cb = g_tbb[ct];   // uniform
            float2 ca = g_tar[ct];
            // stage 2: any query individually overlaps this tile?
            bool qact = qon;
            if (qact) {
                float bw = __fadd_rn(__fsub_rn(fminf(x2, cb.z), fmaxf(x1, cb.x)), 1.0f);
                float bh = __fadd_rn(__fsub_rn(fminf(y2, cb.w), fmaxf(y1, cb.y)), 1.0f);
                float lo = fminf(ai, ca.y);
                float hi = fmaxf(ai, ca.x);
                qact = (bw > 0.f) && (bh > 0.f) && (lo > 0.299f * hi);
            }
            if (!__ballot_sync(FULLM, qact)) continue;
            // load candidates once (coalesced)
            int j = (ct << 5) + lane;
            bool jon = j < kcnt;
            float2 jca = jon ? g_cra[j] : make_float2(0.f, __int_as_float(0x7FFFFFFF));
            float4 jbb = jon ? g_cbox[j] : make_float4(0.f, 0.f, 0.f, 0.f);
            float aj0 = jca.x;
            int rj0 = __float_as_int(jca.y);
            // stage 3: per-candidate prefilter vs query-tile aggregate
            bool jpass = jon && (rj0 < rimax);
            if (jpass) {
                float bw = __fadd_rn(__fsub_rn(fminf(jbb.z, qb.z), fmaxf(jbb.x, qb.x)), 1.0f);
                float bh = __fadd_rn(__fsub_rn(fminf(jbb.w, qb.w), fmaxf(jbb.y, qb.y)), 1.0f);
                jpass = (bw > 0.f) && (bh > 0.f) &&
                        (fminf(aj0, qa.y) > 0.299f * fmaxf(aj0, qa.x));
            }
            unsigned jb = __ballot_sync(FULLM, jpass);
            while (jb) {
                int k = __ffs(jb) - 1;
                jb &= jb - 1;
                float ajk = __shfl_sync(FULLM, aj0, k);
                int   rjk = __shfl_sync(FULLM, rj0, k);
                float bx1 = __shfl_sync(FULLM, jbb.x, k);
                float by1 = __shfl_sync(FULLM, jbb.y, k);
                float bx2 = __shfl_sync(FULLM, jbb.z, k);
                float by2 = __shfl_sync(FULLM, jbb.w, k);
                if (rjk < ri && fminf(ai, ajk) > 0.299f * fmaxf(ai, ajk)) {
                    float xx1 = fmaxf(x1, bx1);
                    float yy1 = fmaxf(y1, by1);
                    float xx2 = fminf(x2, bx2);
                    float yy2 = fminf(y2, by2);
                    float w  = fmaxf(__fadd_rn(__fsub_rn(xx2, xx1), 1.f), 0.f);
                    float hh = fmaxf(__fadd_rn(__fsub_rn(yy2, yy1), 1.f), 0.f);
                    float inter = __fmul_rn(w, hh);
                    if (inter > 0.299f * fmaxf(ai, ajk)) {
                        float iou = __fdiv_rn(inter, __fsub_rn(__fadd_rn(ai, ajk), inter));
                        if (iou > NMS_THF) {
                            if (cnt < SEGCAP)
                                g_nbr[((size_t)ri * NCHUNK + chunk) * SEGCAP + cnt] =
                                    (unsigned short)rjk;
                            cnt++;
                        }
                    }
                }
            }
        }
    }
    if (qon) g_ncnt8[ri * NCHUNK + chunk] = (unsigned char)min(cnt, SEGCAP);
}

// ---------------- K6: dataflow NMS resolve + output write (+ hist re-zero) ----------------
// dependency edges always point to strictly lower ranks -> DAG -> no deadlock.
__global__ void __launch_bounds__(256) k_resolve(float* __restrict__ out) {
    int gid = blockIdx.x * 256 + threadIdx.x;
    if (gid < NDIG) g_hist[gid] = 0;   // reset for next replay
    int gw = gid >> 5;
    int lane = threadIdx.x & 31;
    int kcnt = g_kcnt;
    for (int r = gw; r < kcnt; r += NRW) {
        unsigned long long cnts = *(const unsigned long long*)&g_ncnt8[r * NCHUNK];
        bool removed = false;
        for (int c = 0; c < NCHUNK && !removed; c++) {
            int cn = (int)((cnts >> (8 * c)) & 255ull);
            const unsigned short* lst = g_nbr + ((size_t)r * NCHUNK + c) * SEGCAP;
            for (int b = 0; b < cn && !removed; b += 32) {
                int e = b + lane;
                int cc = (e < cn) ? (int)lst[e] : 0;
                bool pend = (e < cn);
                bool kept = false;
                for (;;) {
                    if (pend) {
                        unsigned long long w = *(volatile unsigned long long*)&g_state[cc >> 5];
                        unsigned long long sv = w >> ((cc & 31) * 2);
                        if (sv & 1ull) { kept = (sv & 2ull) != 0ull; pend = false; }
                    }
                    if (__ballot_sync(FULLM, kept)) { removed = true; break; }
                    if (!__ballot_sync(FULLM, pend)) break;
                    __nanosleep(32);
                }
            }
        }
        if (lane == 0) {
            atomicOr(&g_state[r >> 5], (removed ? 1ull : 3ull) << ((r & 31) * 2));
            int idx = g_ridx[r];
            float f = removed ? 0.0f : 1.0f;
            float4 bb = g_box[idx];
            out[idx * 5 + 0] = __fmul_rn(bb.x, f);
            out[idx * 5 + 1] = __fmul_rn(bb.y, f);
            out[idx * 5 + 2] = __fmul_rn(bb.z, f);
            out[idx * 5 + 3] = __fmul_rn(bb.w, f);
            out[idx * 5 + 4] = __fmul_rn(g_sc[idx], f);
        }
    }
}

extern "C" void kernel_launch(void* const* d_in, const int* in_sizes, int n_in,
                              void* d_out, int out_size) {
    (void)in_sizes; (void)n_in; (void)out_size;
    InPtrs p;
    for (int i = 0; i < 6; i++) {
        p.cls[i] = (const float*)d_in[2 * i];
        p.reg[i] = (const float*)d_in[2 * i + 1];
    }
    float* out = (float*)d_out;
    k_decode<<<NBLK, 256>>>(p, out);
    k_scan<<<1, 1024>>>();
    k_scatter<<<NBLK, 256>>>();
    k_binsort<<<NDIG / 8 + (NCTILE + 7) / 8, 256>>>();
    k_nbr<<<NCTILE, 256>>>();   // NCTILE*8 warps cover all (query-tile, chunk) pairs
    k_resolve<<<NRB, 256>>>(out);
}

// round 16
// speedup vs baseline: 1.3864x; 1.3864x over previous
#include <cuda_runtime.h>
#include <math.h>

#define N_ANCH 21840
#define NCTILE 683            // max compacted tiles = ceil(21840/32)
#define NSTATE 683            // ceil(21840/32), 2 bits per rank
#define NBLK   86             // ceil(21840/256)
#define NDIG   2048           // 11-bit digit space (valid keys only reach 0x7FF)
#define CAP    192            // max higher-rank suppressors per box
#define NRB    64             // resolve blocks
#define NRW    (NRB * 8)      // resolve warps
#define NMS_THF 0.3f
#define FIN_THF 0.5f
#define FULLM 0xFFFFFFFFu

// ---- static device scratch (zero at module load; g_hist/g_state re-zeroed per replay) ----
__device__ float4 g_box[N_ANCH];        // x1,y1,x2,y2 (by original index)
__device__ float g_sc[N_ANCH];
__device__ unsigned g_key[N_ANCH];
__device__ int g_bcnt[NBLK], g_boff[NBLK];
__device__ int g_hist[NDIG];            // re-zeroed by k_resolve each replay
__device__ int g_base[NDIG], g_cursor[NDIG];
__device__ unsigned g_bin[N_ANCH];      // (low12 << 15) | cpos
__device__ float4 g_cbox[N_ANCH];       // compacted valid boxes (index order)
__device__ float2 g_cra[N_ANCH];        // cpos -> (area, rank-as-int-bits)
__device__ unsigned short g_cidx[N_ANCH];  // cpos -> original index
__device__ unsigned short g_ridx[N_ANCH];  // rank -> original index
__device__ int g_kcnt;
__device__ float4 g_tbb[NCTILE];        // compacted tile bbox
__device__ float2 g_tar[NCTILE];        // compacted tile area min/max
__device__ unsigned short g_nbr[(size_t)N_ANCH * CAP];  // by rank
__device__ int g_ncnt[N_ANCH];                           // by rank
__device__ unsigned long long g_state[NSTATE];           // 2 bits/rank (resolved, kept)

struct InPtrs { const float* cls[6]; const float* reg[6]; };

// exact area formula shared by all phases (bit-identical everywhere)
__device__ __forceinline__ float box_area(float x1, float y1, float x2, float y2) {
    return __fmul_rn(__fadd_rn(__fsub_rn(x2, x1), 1.0f),
                     __fadd_rn(__fsub_rn(y2, y1), 1.0f));
}

// ---------------- K1: decode (bit-exact) + key + hist + block valid count ----------------
__global__ void k_decode(InPtrs in, float* __restrict__ out) {
    __shared__ int bc;
    int t = threadIdx.x;
    int i = blockIdx.x * 256 + t;
    int lane = t & 31;
    bool on = i < N_ANCH;
    if (t == 0) bc = 0;
    __syncthreads();

    bool valid = false;
    if (on) {
        const int offs[7]   = {0, 16384, 20480, 21504, 21760, 21824, 21840};
        const int maps[6]   = {128, 64, 32, 16, 8, 4};
        const float strd[6] = {4.f, 8.f, 16.f, 32.f, 64.f, 128.f};
        int sc = 0;
        #pragma unroll
        for (int k = 0; k < 5; k++) if (i >= offs[k + 1]) sc = k + 1;
        int local = i - offs[sc];
        int W = maps[sc];
        int y = local / W, x = local - y * W;
        int HW = W * W;
        const float* cls = in.cls[sc];
        const float* reg = in.reg[sc];

        float c0 = cls[local], c1 = cls[HW + local];
        float m  = fmaxf(c0, c1);
        float e0 = expf(__fsub_rn(c0, m));
        float e1 = expf(__fsub_rn(c1, m));
        float prob = __fdiv_rn(e1, __fadd_rn(e0, e1));

        float s   = strd[sc];
        float pwh = s * 4.0f;
        float pcx = __fadd_rn(0.5f * s, __fmul_rn((float)x, s));
        float pcy = __fadd_rn(0.5f * s, __fmul_rn((float)y, s));
        float l0 = reg[local], l1 = reg[HW + local];
        float l2 = reg[2 * HW + local], l3 = reg[3 * HW + local];
        float cx = __fadd_rn(pcx, __fmul_rn(__fmul_rn(l0, 0.1f), pwh));
        float cy = __fadd_rn(pcy, __fmul_rn(__fmul_rn(l1, 0.1f), pwh));
        float w  = __fmul_rn(pwh, expf(__fmul_rn(l2, 0.2f)));
        float h  = __fmul_rn(pwh, expf(__fmul_rn(l3, 0.2f)));
        float x1 = __fsub_rn(cx, __fmul_rn(w, 0.5f));
        float y1 = __fsub_rn(cy, __fmul_rn(h, 0.5f));
        float x2 = __fadd_rn(x1, w);
        float y2 = __fadd_rn(y1, h);

        g_box[i] = make_float4(x1, y1, x2, y2);
        g_sc[i] = prob;

        // 24-bit key: prob in (0.5,1] -> [0, 0x7FFFFF]; ascending == descending score
        unsigned u   = __float_as_uint(prob);
        unsigned k24 = (~(u | 0x80000000u)) - 0x407FFFFFu;
        valid = prob > FIN_THF;
        g_key[i] = valid ? k24 : 0xFFFFFFFFu;
        if (valid) {
            atomicAdd(&g_hist[k24 >> 12], 1);
        } else {
            // invalid boxes are never kept: write their zero rows now
            out[i * 5 + 0] = 0.f; out[i * 5 + 1] = 0.f; out[i * 5 + 2] = 0.f;
            out[i * 5 + 3] = 0.f; out[i * 5 + 4] = 0.f;
        }
    }
    unsigned bal = __ballot_sync(FULLM, valid);
    if (lane == 0) atomicAdd(&bc, __popc(bal));
    __syncthreads();
    if (t == 0) g_bcnt[blockIdx.x] = bc;
}

// ---------------- K2: exclusive scans (2048 digits + 86 block counts) ----------------
__global__ void __launch_bounds__(1024) k_scan() {
    __shared__ int wsum[32];
    int t = threadIdx.x, lane = t & 31, wid = t >> 5;

    // side job (warp 1): exclusive scan of 86 per-block valid counts
    if (wid == 1) {
        int v0 = (lane < NBLK) ? g_bcnt[lane] : 0;
        int v1 = (lane + 32 < NBLK) ? g_bcnt[lane + 32] : 0;
        int v2 = (lane + 64 < NBLK) ? g_bcnt[lane + 64] : 0;
        int s0 = v0, s1 = v1, s2 = v2;
        #pragma unroll
        for (int k = 1; k < 32; k <<= 1) {
            int a = __shfl_up_sync(FULLM, s0, k); if (lane >= k) s0 += a;
            int b = __shfl_up_sync(FULLM, s1, k); if (lane >= k) s1 += b;
            int c = __shfl_up_sync(FULLM, s2, k); if (lane >= k) s2 += c;
        }
        int t0 = __shfl_sync(FULLM, s0, 31);
        int t1 = __shfl_sync(FULLM, s1, 31);
        if (lane < NBLK) g_boff[lane] = s0 - v0;
        if (lane + 32 < NBLK) g_boff[lane + 32] = t0 + s1 - v1;
        if (lane + 64 < NBLK) g_boff[lane + 64] = t0 + t1 + s2 - v2;
    }

    int a0 = g_hist[2 * t], a1 = g_hist[2 * t + 1];
    int s = a0 + a1;
    int x = s;
    #pragma unroll
    for (int k = 1; k < 32; k <<= 1) { int y = __shfl_up_sync(FULLM, x, k); if (lane >= k) x += y; }
    if (lane == 31) wsum[wid] = x;
    __syncthreads();
    if (wid == 0) {
        int wv = wsum[lane];
        #pragma unroll
        for (int k = 1; k < 32; k <<= 1) { int y = __shfl_up_sync(FULLM, wv, k); if (lane >= k) wv += y; }
        wsum[lane] = wv;
    }
    __syncthreads();
    int base = x - s + ((wid > 0) ? wsum[wid - 1] : 0);
    g_base[2 * t] = base;          g_cursor[2 * t] = base;
    g_base[2 * t + 1] = base + a0; g_cursor[2 * t + 1] = base + a0;
    if (t == 1023) g_kcnt = base + s;   // total valid
}

// ---------------- K3: bin scatter + ordered compaction (+ state zero) ----------------
__global__ void k_scatter() {
    __shared__ int wscan[8];
    if (blockIdx.x == 0) {
        for (int w = threadIdx.x; w < NSTATE; w += 256) g_state[w] = 0ull;
    }
    int t = threadIdx.x, lane = t & 31, wid = t >> 5;
    int i = blockIdx.x * 256 + t;
    bool on = i < N_ANCH;
    unsigned k = on ? g_key[i] : 0xFFFFFFFFu;
    bool valid = (k != 0xFFFFFFFFu);

    unsigned bal = __ballot_sync(FULLM, valid);
    if (lane == 0) wscan[wid] = __popc(bal);
    __syncthreads();
    if (t == 0) {
        int run = 0;
        #pragma unroll
        for (int w = 0; w < 8; w++) { int c = wscan[w]; wscan[w] = run; run += c; }
    }
    __syncthreads();

    if (valid) {
        int cpos = g_boff[blockIdx.x] + wscan[wid] + __popc(bal & ((1u << lane) - 1));
        float4 b = g_box[i];
        g_cbox[cpos] = b;
        g_cra[cpos] = make_float2(box_area(b.x, b.y, b.z, b.w), 0.f);  // rank patched by binsort
        g_cidx[cpos] = (unsigned short)i;
        int d = k >> 12;
        int pos = atomicAdd(&g_cursor[d], 1);
        g_bin[pos] = ((k & 0xFFFu) << 15) | (unsigned)cpos;   // cpos monotone in idx -> stable ties
    }
}

// ---------------- K4: in-bin ranking (warp per bin) + compacted tile bboxes ----------------
__global__ void k_binsort() {
    int wid = threadIdx.x >> 5, lane = threadIdx.x & 31;
    int gw = blockIdx.x * 8 + wid;
    int* rankslot = (int*)g_cra;   // rank lives in .y of float2
    if (gw < NDIG) {
        int d = gw;
        int base = g_base[d];
        int n = g_cursor[d] - base;
        if (n == 0) return;
        if (n <= 32) {
            unsigned rec = (lane < n) ? g_bin[base + lane] : 0xFFFFFFFFu;
            int r = 0;
            for (int k = 0; k < n; k++) {
                unsigned other = __shfl_sync(FULLM, rec, k);
                r += (other < rec) ? 1 : 0;
            }
            if (lane < n) {
                int cpos = rec & 0x7FFFu;
                int rank = base + r;
                rankslot[2 * cpos + 1] = rank;
                g_ridx[rank] = g_cidx[cpos];
            }
        } else {
            for (int e = lane; e < n; e += 32) {
                unsigned rec = g_bin[base + e];
                int r = 0;
                for (int k = 0; k < n; k++) r += (g_bin[base + k] < rec) ? 1 : 0;
                int cpos = rec & 0x7FFFu;
                int rank = base + r;
                rankslot[2 * cpos + 1] = rank;
                g_ridx[rank] = g_cidx[cpos];
            }
        }
    } else {
        // tile-bbox warps over the compacted array
        int tile = gw - NDIG;
        if (tile >= NCTILE) return;
        int kcnt = g_kcnt;
        int kk = tile * 32 + lane;
        bool on = kk < kcnt;
        float x1 = 0.f, y1 = 0.f, x2 = 0.f, y2 = 0.f, area = 0.f;
        if (on) {
            float4 b = g_cbox[kk];
            x1 = b.x; y1 = b.y; x2 = b.z; y2 = b.w;
            area = box_area(x1, y1, x2, y2);
        }
        float r0 = on ? x1 :  1e30f;
        float r1 = on ? y1 :  1e30f;
        float r2 = on ? x2 : -1e30f;
        float r3 = on ? y2 : -1e30f;
        float r4 = on ? area :  1e30f;
        float r5 = on ? area : -1e30f;
        #pragma unroll
        for (int s = 16; s > 0; s >>= 1) {
            r0 = fminf(r0, __shfl_xor_sync(FULLM, r0, s));
            r1 = fminf(r1, __shfl_xor_sync(FULLM, r1, s));
            r2 = fmaxf(r2, __shfl_xor_sync(FULLM, r2, s));
            r3 = fmaxf(r3, __shfl_xor_sync(FULLM, r3, s));
            r4 = fminf(r4, __shfl_xor_sync(FULLM, r4, s));
            r5 = fmaxf(r5, __shfl_xor_sync(FULLM, r5, s));
        }
        if (lane == 0) {
            g_tbb[tile] = make_float4(r0, r1, r2, r3);
            g_tar[tile] = make_float2(r4, r5);
        }
    }
}

// ---------------- K5: sparse suppressor lists (warp per compacted box) ----------------
// candidate gate: one 8B load (area, rank); rank + area-ratio reject before 16B box load.
// IoU <= min(area)/max(area) under monotone rn rounding, so ratio <= 0.299 can never
// produce iou > 0.3 (slack 0.3/0.299 >> rounding).
__global__ void k_nbr() {
    int kq = (blockIdx.x * blockDim.x + threadIdx.x) >> 5;
    int lane = threadIdx.x & 31;
    int kcnt = g_kcnt;
    if (kq >= kcnt) return;
    float2 me = g_cra[kq];
    float ai = me.x;
    int ri = __float_as_int(me.y);
    float4 bb = g_cbox[kq];
    float x1 = bb.x, y1 = bb.y, x2 = bb.z, y2 = bb.w;
    int ntile = (kcnt + 31) >> 5;
    int cnt = 0;
    for (int tb = 0; tb < ntile; tb += 32) {
        int t = tb + lane;
        bool act = false;
        if (t < ntile) {
            float4 tbv = g_tbb[t];
            float2 tav = g_tar[t];
            float bw = __fadd_rn(__fsub_rn(fminf(x2, tbv.z), fmaxf(x1, tbv.x)), 1.0f);
            float bh = __fadd_rn(__fsub_rn(fminf(y2, tbv.w), fmaxf(y1, tbv.y)), 1.0f);
            float lo = fminf(ai, tav.y);
            float hi = fmaxf(ai, tav.x);
            act = (bw > 0.f) && (bh > 0.f) && (lo > 0.299f * hi);  // conservative
        }
        unsigned bal = __ballot_sync(FULLM, act);
        while (bal) {
            int tt = __ffs(bal) - 1;
            bal &= bal - 1;
            int j = ((tb + tt) << 5) + lane;
            bool hit = false;
            int rj = 0x7FFFFFFF;
            if (j < kcnt) {
                float2 ca = g_cra[j];
                rj = __float_as_int(ca.y);
                float aj = ca.x;
                if (rj < ri && fminf(ai, aj) > 0.299f * fmaxf(ai, aj)) {
                    float4 bj = g_cbox[j];
                    float xx1 = fmaxf(x1, bj.x);
                    float yy1 = fmaxf(y1, bj.y);
                    float xx2 = fminf(x2, bj.z);
                    float yy2 = fminf(y2, bj.w);
                    float w  = fmaxf(__fadd_rn(__fsub_rn(xx2, xx1), 1.f), 0.f);
                    float hh = fmaxf(__fadd_rn(__fsub_rn(yy2, yy1), 1.f), 0.f);
                    float inter = __fmul_rn(w, hh);
                    if (inter > 0.299f * fmaxf(ai, aj)) {
                        float iou = __fdiv_rn(inter, __fsub_rn(__fadd_rn(ai, aj), inter));
                        hit = iou > NMS_THF;
                    }
                }
            }
            unsigned hb = __ballot_sync(FULLM, hit);
            if (hit) {
                int off = cnt + __popc(hb & ((1u << lane) - 1));
                if (off < CAP) g_nbr[(size_t)ri * CAP + off] = (unsigned short)rj;
            }
            cnt += __popc(hb);
        }
    }
    if (lane == 0) g_ncnt[ri] = min(cnt, CAP);
}

// ---------------- K6: dataflow NMS resolve + output write (+ hist re-zero) ----------------
// dependency edges always point to strictly lower ranks -> DAG -> no deadlock.
__global__ void __launch_bounds__(256) k_resolve(float* __restrict__ out) {
    int gid = blockIdx.x * 256 + threadIdx.x;
    if (gid < NDIG) g_hist[gid] = 0;   // reset for next replay
    int gw = gid >> 5;
    int lane = threadIdx.x & 31;
    int kcnt = g_kcnt;
    for (int r = gw; r < kcnt; r += NRW) {
        int cn = g_ncnt[r];
        const unsigned short* lst = g_nbr + (size_t)r * CAP;
        bool removed = false;
        for (int b = 0; b < cn && !removed; b += 32) {
            int e = b + lane;
            int c = (e < cn) ? (int)lst[e] : 0;
            bool pend = (e < cn);
            bool kept = false;
            for (;;) {
                if (pend) {
                    unsigned long long w = *(volatile unsigned long long*)&g_state[c >> 5];
                    unsigned long long sv = w >> ((c & 31) * 2);
                    if (sv & 1ull) { kept = (sv & 2ull) != 0ull; pend = false; }
                }
                if (__ballot_sync(FULLM, kept)) { removed = true; break; }
                if (!__ballot_sync(FULLM, pend)) break;
                __nanosleep(32);
            }
        }
        if (lane == 0) {
            atomicOr(&g_state[r >> 5], (removed ? 1ull : 3ull) << ((r & 31) * 2));
            int idx = g_ridx[r];
            float f = removed ? 0.0f : 1.0f;
            float4 bb = g_box[idx];
            out[idx * 5 + 0] = __fmul_rn(bb.x, f);
            out[idx * 5 + 1] = __fmul_rn(bb.y, f);
            out[idx * 5 + 2] = __fmul_rn(bb.z, f);
            out[idx * 5 + 3] = __fmul_rn(bb.w, f);
            out[idx * 5 + 4] = __fmul_rn(g_sc[idx], f);
        }
    }
}

extern "C" void kernel_launch(void* const* d_in, const int* in_sizes, int n_in,
                              void* d_out, int out_size) {
    (void)in_sizes; (void)n_in; (void)out_size;
    InPtrs p;
    for (int i = 0; i < 6; i++) {
        p.cls[i] = (const float*)d_in[2 * i];
        p.reg[i] = (const float*)d_in[2 * i + 1];
    }
    float* out = (float*)d_out;
    k_decode<<<NBLK, 256>>>(p, out);
    k_scan<<<1, 1024>>>();
    k_scatter<<<NBLK, 256>>>();
    k_binsort<<<NDIG / 8 + (NCTILE + 7) / 8, 256>>>();
    k_nbr<<<(N_ANCH * 32 + 255) / 256, 256>>>();
    k_resolve<<<NRB, 256>>>(out);
}